// round 1
// baseline (speedup 1.0000x reference)
#include <cuda_runtime.h>

#define N_NODES 40000
#define D 128
#define N_EDGES 640000
#define HASH_BITS 21
#define HASH_SIZE (1u << HASH_BITS)
#define HASH_MASK (HASH_SIZE - 1u)
#define HKEY_EMPTY 0xFFFFFFFFu

// Scratch (no allocations allowed): ~49.5 MB total
__device__ unsigned int g_hash[HASH_SIZE];
__device__ float g_deg[N_NODES];
__device__ float g_dinv[N_NODES];
__device__ float g_y[2 * N_NODES * D];   // [0 .. N*D) = y_re, [N*D .. 2*N*D) = y_im
__device__ float g_W[D * D];             // 0.5*(W1+W2)
__device__ float g_bias[D];              // 0.5*(b1+b2)

__device__ __forceinline__ unsigned hash_u32(unsigned key) {
    return (key * 2654435761u) >> (32 - HASH_BITS);
}

__device__ __forceinline__ void red_add_v4(float* p, float4 v) {
    asm volatile("red.global.add.v4.f32 [%0], {%1, %2, %3, %4};"
                 :: "l"(p), "f"(v.x), "f"(v.y), "f"(v.z), "f"(v.w)
                 : "memory");
}

// ---------------------------------------------------------------------------
// 1. Init scratch: hash -> EMPTY, deg -> 0, y -> 0
// ---------------------------------------------------------------------------
__global__ void k_init() {
    unsigned i = blockIdx.x * blockDim.x + threadIdx.x;
    unsigned stride = gridDim.x * blockDim.x;
    for (unsigned j = i; j < HASH_SIZE; j += stride) g_hash[j] = HKEY_EMPTY;
    const unsigned ytot = 2u * N_NODES * D;
    float4* y4 = reinterpret_cast<float4*>(g_y);
    for (unsigned j = i; j < ytot / 4; j += stride) y4[j] = make_float4(0.f, 0.f, 0.f, 0.f);
    for (unsigned j = i; j < N_NODES; j += stride) g_deg[j] = 0.f;
}

// ---------------------------------------------------------------------------
// 2. Fold the two linear layers (ALPHA = 0.5)
// ---------------------------------------------------------------------------
__global__ void k_weights(const float* __restrict__ W1, const float* __restrict__ b1,
                          const float* __restrict__ W2, const float* __restrict__ b2) {
    int i = blockIdx.x * blockDim.x + threadIdx.x;
    if (i < D * D) g_W[i] = 0.5f * (W1[i] + W2[i]);
    if (i < D) g_bias[i] = 0.5f * (b1[i] + b2[i]);
}

// ---------------------------------------------------------------------------
// 3. Insert edge keys into hash set + accumulate symmetrized degree
// ---------------------------------------------------------------------------
__global__ void k_insert(const int* __restrict__ ei) {
    int e = blockIdx.x * blockDim.x + threadIdx.x;
    if (e >= N_EDGES) return;
    unsigned row = (unsigned)ei[e];
    unsigned col = (unsigned)ei[N_EDGES + e];
    unsigned key = row * (unsigned)N_NODES + col;
    unsigned h = hash_u32(key);
    while (true) {
        unsigned prev = atomicCAS(&g_hash[h], HKEY_EMPTY, key);
        if (prev == HKEY_EMPTY || prev == key) break;
        h = (h + 1u) & HASH_MASK;
    }
    atomicAdd(&g_deg[row], 0.5f);
    atomicAdd(&g_deg[col], 0.5f);
}

// ---------------------------------------------------------------------------
// 4. dinv = deg > 0 ? rsqrt(deg) : 0
// ---------------------------------------------------------------------------
__global__ void k_dinv() {
    int i = blockIdx.x * blockDim.x + threadIdx.x;
    if (i >= N_NODES) return;
    float d = g_deg[i];
    g_dinv[i] = (d > 0.f) ? rsqrtf(d) : 0.f;
}

// ---------------------------------------------------------------------------
// 5. SpMM: one warp per directed edge.
//    has_rev -> both copies feed y_re with +s
//    else    -> forward feeds y_im with +s, reverse feeds y_im with -s
//    (cos/sin collapse to {0, +-1} because 2*pi*Q = pi/2)
// ---------------------------------------------------------------------------
__global__ void k_spmm(const int* __restrict__ ei, const float* __restrict__ x) {
    unsigned gtid = blockIdx.x * blockDim.x + threadIdx.x;
    unsigned e = gtid >> 5;
    unsigned lane = threadIdx.x & 31u;
    if (e >= N_EDGES) return;

    int row = ei[e];
    int col = ei[N_EDGES + e];

    float s = 0.f;
    unsigned found = 0;
    if (lane == 0) {
        unsigned rkey = (unsigned)col * (unsigned)N_NODES + (unsigned)row;
        unsigned h = hash_u32(rkey);
        unsigned v;
        while ((v = g_hash[h]) != HKEY_EMPTY && v != rkey) h = (h + 1u) & HASH_MASK;
        found = (v == rkey) ? 1u : 0u;
        s = 0.5f * g_dinv[row] * g_dinv[col];
    }
    found = __shfl_sync(0xFFFFFFFFu, found, 0);
    s = __shfl_sync(0xFFFFFFFFu, s, 0);

    const float4* x4 = reinterpret_cast<const float4*>(x);
    float4 xc = x4[(size_t)col * (D / 4) + lane];   // x[col]
    float4 xr = x4[(size_t)row * (D / 4) + lane];   // x[row]

    float* ybase = found ? g_y : (g_y + (size_t)N_NODES * D);
    float srev = found ? s : -s;

    float4 vf = make_float4(s * xc.x, s * xc.y, s * xc.z, s * xc.w);
    float4 vr = make_float4(srev * xr.x, srev * xr.y, srev * xr.z, srev * xr.w);

    red_add_v4(ybase + (size_t)row * D + lane * 4, vf);
    red_add_v4(ybase + (size_t)col * D + lane * 4, vr);
}

// ---------------------------------------------------------------------------
// 6. GEMM: out = Y[80000,128] @ W[128,128] + b, with re/im output interleave.
//    64x128 tile, BK=32, 256 threads, 8x4 register micro-tile per thread.
// ---------------------------------------------------------------------------
__global__ void k_gemm(float* __restrict__ out) {
    __shared__ float As[64 * 32];       // [row][k]
    __shared__ float Bs[32 * 128];      // [k][col]

    const int tid = threadIdx.x;
    const int tx = tid & 31;            // col group: 32 groups of 4 cols
    const int ty = tid >> 5;            // row group: 8 groups of 8 rows
    const int block_row = blockIdx.x * 64;

    float acc[8][4];
#pragma unroll
    for (int i = 0; i < 8; i++)
#pragma unroll
        for (int j = 0; j < 4; j++) acc[i][j] = 0.f;

    const float4* Y4 = reinterpret_cast<const float4*>(g_y);
    const float4* W4 = reinterpret_cast<const float4*>(g_W);
    float4* As4 = reinterpret_cast<float4*>(As);
    float4* Bs4 = reinterpret_cast<float4*>(Bs);

#pragma unroll
    for (int kb = 0; kb < D / 32; kb++) {
        // Load A tile: 64 rows x 32 k = 512 float4; 2 per thread
#pragma unroll
        for (int q = 0; q < 2; q++) {
            int idx = tid + 256 * q;            // [0,512)
            int r = idx >> 3;                   // 8 float4 per row
            int kp = idx & 7;
            As4[r * 8 + kp] = Y4[(size_t)(block_row + r) * (D / 4) + kb * 8 + kp];
        }
        // Load B tile: 32 k x 128 cols = 1024 float4; 4 per thread
#pragma unroll
        for (int q = 0; q < 4; q++) {
            int idx = tid + 256 * q;            // [0,1024)
            int r = idx >> 5;                   // 32 float4 per row
            int c4 = idx & 31;
            Bs4[r * 32 + c4] = W4[(size_t)(kb * 32 + r) * (D / 4) + c4];
        }
        __syncthreads();

#pragma unroll
        for (int kk = 0; kk < 32; kk++) {
            float a_[8];
#pragma unroll
            for (int i = 0; i < 8; i++) a_[i] = As[(ty * 8 + i) * 32 + kk];
            float4 b_ = Bs4[kk * 32 + tx];
#pragma unroll
            for (int i = 0; i < 8; i++) {
                acc[i][0] = fmaf(a_[i], b_.x, acc[i][0]);
                acc[i][1] = fmaf(a_[i], b_.y, acc[i][1]);
                acc[i][2] = fmaf(a_[i], b_.z, acc[i][2]);
                acc[i][3] = fmaf(a_[i], b_.w, acc[i][3]);
            }
        }
        __syncthreads();
    }

    float4 bias = reinterpret_cast<const float4*>(g_bias)[tx];

#pragma unroll
    for (int i = 0; i < 8; i++) {
        int g = block_row + ty * 8 + i;          // [0, 80000)
        size_t o;
        if (g < N_NODES) o = (size_t)g * (2 * D) + tx * 4;                    // real half
        else             o = (size_t)(g - N_NODES) * (2 * D) + D + tx * 4;    // imag half
        float4 v = make_float4(acc[i][0] + bias.x, acc[i][1] + bias.y,
                               acc[i][2] + bias.z, acc[i][3] + bias.w);
        *reinterpret_cast<float4*>(out + o) = v;
    }
}

// ---------------------------------------------------------------------------
extern "C" void kernel_launch(void* const* d_in, const int* in_sizes, int n_in,
                              void* d_out, int out_size) {
    const float* x  = (const float*)d_in[0];
    const int*   ei = (const int*)d_in[1];
    const float* W1 = (const float*)d_in[2];
    const float* b1 = (const float*)d_in[3];
    const float* W2 = (const float*)d_in[4];
    const float* b2 = (const float*)d_in[5];
    float* out = (float*)d_out;

    k_init<<<2048, 256>>>();
    k_weights<<<(D * D + 255) / 256, 256>>>(W1, b1, W2, b2);
    k_insert<<<(N_EDGES + 255) / 256, 256>>>(ei);
    k_dinv<<<(N_NODES + 255) / 256, 256>>>();
    k_spmm<<<N_EDGES / 8, 256>>>(ei, x);     // 1 warp/edge, 8 warps/block
    k_gemm<<<(2 * N_NODES) / 64, 256>>>(out);
}

// round 2
// speedup vs baseline: 1.3784x; 1.3784x over previous
#include <cuda_runtime.h>

#define N_NODES 40000
#define D 128
#define N_EDGES 640000
#define HASH_BITS 21
#define HASH_SIZE (1u << HASH_BITS)
#define HASH_MASK (HASH_SIZE - 1u)
#define HKEY_EMPTY 0xFFFFFFFFu
#define SCAN_B 256
#define NSCAN_BLK ((N_NODES + SCAN_B - 1) / SCAN_B)   // 157

// ---- scratch (~36 MB, no allocations allowed) ----
__device__ unsigned g_hash[HASH_SIZE];
__device__ int g_cnt[N_NODES];           // symmetrized incidence count (deg = 0.5*cnt)
__device__ int g_off[N_NODES + 1];       // CSR offsets
__device__ int g_next[N_NODES];          // scatter cursors
__device__ int g_bsum[NSCAN_BLK];
__device__ int g_boff[NSCAN_BLK];
__device__ unsigned g_ent[2 * N_EDGES];  // packed: src(16) | has_rev(1)<<16 | neg(1)<<17
__device__ float g_dinv[N_NODES];
__device__ float g_Z[N_NODES * D];       // Z = x @ W
__device__ float g_W[D * D];             // 0.5*(W1+W2)
__device__ float g_bias[D];              // 0.5*(b1+b2)

__device__ __forceinline__ unsigned hash_u32(unsigned key) {
    return (key * 2654435761u) >> (32 - HASH_BITS);
}

// ---------------------------------------------------------------------------
// 1. init: hash -> EMPTY, cnt -> 0
// ---------------------------------------------------------------------------
__global__ void k_init() {
    unsigned i = blockIdx.x * blockDim.x + threadIdx.x;
    unsigned stride = gridDim.x * blockDim.x;
    for (unsigned j = i; j < HASH_SIZE; j += stride) g_hash[j] = HKEY_EMPTY;
    for (unsigned j = i; j < N_NODES; j += stride) g_cnt[j] = 0;
}

// ---------------------------------------------------------------------------
// 2. fold the two linear layers (ALPHA = 0.5)
// ---------------------------------------------------------------------------
__global__ void k_weights(const float* __restrict__ W1, const float* __restrict__ b1,
                          const float* __restrict__ W2, const float* __restrict__ b2) {
    int i = blockIdx.x * blockDim.x + threadIdx.x;
    if (i < D * D) g_W[i] = 0.5f * (W1[i] + W2[i]);
    if (i < D) g_bias[i] = 0.5f * (b1[i] + b2[i]);
}

// ---------------------------------------------------------------------------
// 3. insert edge keys into hash set + symmetrized incidence histogram
// ---------------------------------------------------------------------------
__global__ void k_insert(const int* __restrict__ ei) {
    int e = blockIdx.x * blockDim.x + threadIdx.x;
    if (e >= N_EDGES) return;
    unsigned row = (unsigned)ei[e];
    unsigned col = (unsigned)ei[N_EDGES + e];
    unsigned key = row * (unsigned)N_NODES + col;
    unsigned h = hash_u32(key);
    while (true) {
        unsigned prev = atomicCAS(&g_hash[h], HKEY_EMPTY, key);
        if (prev == HKEY_EMPTY || prev == key) break;
        h = (h + 1u) & HASH_MASK;
    }
    atomicAdd(&g_cnt[row], 1);
    atomicAdd(&g_cnt[col], 1);
}

// ---------------------------------------------------------------------------
// 4. exclusive scan of g_cnt -> g_off / g_next  (3 tiny kernels)
// ---------------------------------------------------------------------------
__global__ void k_scan_a() {
    __shared__ int sh[SCAN_B];
    int i = blockIdx.x * SCAN_B + threadIdx.x;
    sh[threadIdx.x] = (i < N_NODES) ? g_cnt[i] : 0;
    __syncthreads();
    for (int s = SCAN_B / 2; s > 0; s >>= 1) {
        if (threadIdx.x < s) sh[threadIdx.x] += sh[threadIdx.x + s];
        __syncthreads();
    }
    if (threadIdx.x == 0) g_bsum[blockIdx.x] = sh[0];
}
__global__ void k_scan_b() {
    if (threadIdx.x == 0) {
        int acc = 0;
        for (int b = 0; b < NSCAN_BLK; b++) { g_boff[b] = acc; acc += g_bsum[b]; }
    }
}
__global__ void k_scan_c() {
    __shared__ int sh[SCAN_B];
    int i = blockIdx.x * SCAN_B + threadIdx.x;
    int v = (i < N_NODES) ? g_cnt[i] : 0;
    sh[threadIdx.x] = v;
    __syncthreads();
    for (int s = 1; s < SCAN_B; s <<= 1) {
        int t = (threadIdx.x >= s) ? sh[threadIdx.x - s] : 0;
        __syncthreads();
        sh[threadIdx.x] += t;
        __syncthreads();
    }
    int excl = sh[threadIdx.x] - v + g_boff[blockIdx.x];
    if (i < N_NODES) { g_off[i] = excl; g_next[i] = excl; }
    if (i == N_NODES - 1) g_off[N_NODES] = excl + v;
}

// ---------------------------------------------------------------------------
// 5. dinv = rsqrt(0.5*cnt)
// ---------------------------------------------------------------------------
__global__ void k_dinv() {
    int i = blockIdx.x * blockDim.x + threadIdx.x;
    if (i >= N_NODES) return;
    int c = g_cnt[i];
    g_dinv[i] = (c > 0) ? rsqrtf(0.5f * (float)c) : 0.f;
}

// ---------------------------------------------------------------------------
// 6. scatter packed CSR entries (probe hash once per directed edge)
//    2*pi*Q = pi/2  =>  has_rev ? real(+s both dirs) : imag(+s fwd, -s rev)
// ---------------------------------------------------------------------------
__global__ void k_scatter(const int* __restrict__ ei) {
    int e = blockIdx.x * blockDim.x + threadIdx.x;
    if (e >= N_EDGES) return;
    unsigned row = (unsigned)ei[e];
    unsigned col = (unsigned)ei[N_EDGES + e];
    unsigned rkey = col * (unsigned)N_NODES + row;
    unsigned h = hash_u32(rkey);
    unsigned v;
    while ((v = g_hash[h]) != HKEY_EMPTY && v != rkey) h = (h + 1u) & HASH_MASK;
    unsigned hr = (v == rkey) ? 0x10000u : 0u;
    int p1 = atomicAdd(&g_next[row], 1);
    g_ent[p1] = col | hr;                 // forward copy into row's list, sign +
    int p2 = atomicAdd(&g_next[col], 1);
    g_ent[p2] = row | hr | 0x20000u;      // reversed copy into col's list, sign -
}

// ---------------------------------------------------------------------------
// 7. Z = x @ W   (40000x128 @ 128x128), 64x128 tile, 256 threads
// ---------------------------------------------------------------------------
__global__ void k_gemm(const float* __restrict__ x) {
    __shared__ float As[64 * 32];
    __shared__ float Bs[32 * 128];

    const int tid = threadIdx.x;
    const int tx = tid & 31;
    const int ty = tid >> 5;
    const int block_row = blockIdx.x * 64;

    float acc[8][4];
#pragma unroll
    for (int i = 0; i < 8; i++)
#pragma unroll
        for (int j = 0; j < 4; j++) acc[i][j] = 0.f;

    const float4* X4 = reinterpret_cast<const float4*>(x);
    const float4* W4 = reinterpret_cast<const float4*>(g_W);
    float4* As4 = reinterpret_cast<float4*>(As);
    float4* Bs4 = reinterpret_cast<float4*>(Bs);

#pragma unroll
    for (int kb = 0; kb < D / 32; kb++) {
#pragma unroll
        for (int q = 0; q < 2; q++) {
            int idx = tid + 256 * q;
            int r = idx >> 3, kp = idx & 7;
            As4[r * 8 + kp] = X4[(size_t)(block_row + r) * (D / 4) + kb * 8 + kp];
        }
#pragma unroll
        for (int q = 0; q < 4; q++) {
            int idx = tid + 256 * q;
            int r = idx >> 5, c4 = idx & 31;
            Bs4[r * 32 + c4] = W4[(size_t)(kb * 32 + r) * (D / 4) + c4];
        }
        __syncthreads();
#pragma unroll
        for (int kk = 0; kk < 32; kk++) {
            float a_[8];
#pragma unroll
            for (int i = 0; i < 8; i++) a_[i] = As[(ty * 8 + i) * 32 + kk];
            float4 b_ = Bs4[kk * 32 + tx];
#pragma unroll
            for (int i = 0; i < 8; i++) {
                acc[i][0] = fmaf(a_[i], b_.x, acc[i][0]);
                acc[i][1] = fmaf(a_[i], b_.y, acc[i][1]);
                acc[i][2] = fmaf(a_[i], b_.z, acc[i][2]);
                acc[i][3] = fmaf(a_[i], b_.w, acc[i][3]);
            }
        }
        __syncthreads();
    }

    float4* Z4 = reinterpret_cast<float4*>(g_Z);
#pragma unroll
    for (int i = 0; i < 8; i++) {
        int g = block_row + ty * 8 + i;
        Z4[(size_t)g * (D / 4) + tx] =
            make_float4(acc[i][0], acc[i][1], acc[i][2], acc[i][3]);
    }
}

// ---------------------------------------------------------------------------
// 8. CSR aggregation: one warp per node. acc_re/acc_im in registers,
//    single write of out row (+bias; degree-0 nodes emit pure bias).
// ---------------------------------------------------------------------------
__global__ void k_spmm_csr(float* __restrict__ out) {
    int u = blockIdx.x * (blockDim.x >> 5) + (threadIdx.x >> 5);
    int lane = threadIdx.x & 31;
    if (u >= N_NODES) return;

    int start = g_off[u];
    int end = g_off[u + 1];
    float du = 0.5f * g_dinv[u];

    const float4* Z4 = reinterpret_cast<const float4*>(g_Z);
    float4 are = make_float4(0.f, 0.f, 0.f, 0.f);
    float4 aim = make_float4(0.f, 0.f, 0.f, 0.f);

    for (int base = start; base < end; base += 32) {
        int idx = base + lane;
        unsigned ent = (idx < end) ? g_ent[idx] : 0u;
        float w = (idx < end) ? g_dinv[ent & 0xFFFFu] : 0.f;
        int n = min(32, end - base);
        for (int j = 0; j < n; j++) {
            unsigned e = __shfl_sync(0xFFFFFFFFu, ent, j);
            float wc = __shfl_sync(0xFFFFFFFFu, w, j);
            int src = (int)(e & 0xFFFFu);
            float4 z = Z4[(size_t)src * (D / 4) + lane];
            float s = du * wc;
            if (e & 0x10000u) {
                are.x = fmaf(s, z.x, are.x); are.y = fmaf(s, z.y, are.y);
                are.z = fmaf(s, z.z, are.z); are.w = fmaf(s, z.w, are.w);
            } else {
                if (e & 0x20000u) s = -s;
                aim.x = fmaf(s, z.x, aim.x); aim.y = fmaf(s, z.y, aim.y);
                aim.z = fmaf(s, z.z, aim.z); aim.w = fmaf(s, z.w, aim.w);
            }
        }
    }

    float4 bias = reinterpret_cast<const float4*>(g_bias)[lane];
    float4* O4 = reinterpret_cast<float4*>(out);
    // out row: [u, 0:128) = re, [u, 128:256) = im ; row = 64 float4
    O4[(size_t)u * 64 + lane] =
        make_float4(are.x + bias.x, are.y + bias.y, are.z + bias.z, are.w + bias.w);
    O4[(size_t)u * 64 + 32 + lane] =
        make_float4(aim.x + bias.x, aim.y + bias.y, aim.z + bias.z, aim.w + bias.w);
}

// ---------------------------------------------------------------------------
extern "C" void kernel_launch(void* const* d_in, const int* in_sizes, int n_in,
                              void* d_out, int out_size) {
    const float* x  = (const float*)d_in[0];
    const int*   ei = (const int*)d_in[1];
    const float* W1 = (const float*)d_in[2];
    const float* b1 = (const float*)d_in[3];
    const float* W2 = (const float*)d_in[4];
    const float* b2 = (const float*)d_in[5];
    float* out = (float*)d_out;

    k_init<<<512, 256>>>();
    k_weights<<<(D * D + 255) / 256, 256>>>(W1, b1, W2, b2);
    k_insert<<<(N_EDGES + 255) / 256, 256>>>(ei);
    k_scan_a<<<NSCAN_BLK, SCAN_B>>>();
    k_scan_b<<<1, 32>>>();
    k_scan_c<<<NSCAN_BLK, SCAN_B>>>();
    k_dinv<<<(N_NODES + 255) / 256, 256>>>();
    k_scatter<<<(N_EDGES + 255) / 256, 256>>>(ei);
    k_gemm<<<N_NODES / 64, 256>>>(x);
    k_spmm_csr<<<(N_NODES + 7) / 8, 256>>>(out);
}

// round 4
// speedup vs baseline: 1.6232x; 1.1776x over previous
#include <cuda_runtime.h>
#include <cuda_fp16.h>

#define N_NODES 40000
#define D 128
#define N_EDGES 640000
#define HASH_BITS 21
#define HASH_SIZE (1u << HASH_BITS)
#define HASH_MASK (HASH_SIZE - 1u)
#define HKEY_EMPTY 0xFFFFFFFFu
#define SCAN_B 256
#define NSCAN_BLK ((N_NODES + SCAN_B - 1) / SCAN_B)   // 157

// ---- scratch (~25 MB, no allocations allowed) ----
__device__ unsigned g_hash[HASH_SIZE];
__device__ int g_cnt[N_NODES];           // symmetrized incidence count (deg = 0.5*cnt)
__device__ int g_off[N_NODES + 1];       // CSR offsets
__device__ int g_next[N_NODES];          // scatter cursors
__device__ int g_bsum[NSCAN_BLK];
__device__ int g_boff[NSCAN_BLK];
__device__ unsigned g_ent[2 * N_EDGES];  // packed: src(16) | has_rev(1)<<16 | neg(1)<<17
__device__ float g_dinv[N_NODES];
__device__ __half g_Zh[N_NODES * D];     // Z = x @ W, fp16 (10 MB, L2-resident)
__device__ float g_W[D * D];             // 0.5*(W1+W2)
__device__ float g_bias[D];              // 0.5*(b1+b2)

__device__ __forceinline__ unsigned hash_u32(unsigned key) {
    return (key * 2654435761u) >> (32 - HASH_BITS);
}

// ---------------------------------------------------------------------------
// 1. init: hash -> EMPTY, cnt -> 0, fold weights (ALPHA = 0.5)
// ---------------------------------------------------------------------------
__global__ void k_init(const float* __restrict__ W1, const float* __restrict__ b1,
                       const float* __restrict__ W2, const float* __restrict__ b2) {
    unsigned i = blockIdx.x * blockDim.x + threadIdx.x;
    unsigned stride = gridDim.x * blockDim.x;
    for (unsigned j = i; j < HASH_SIZE; j += stride) g_hash[j] = HKEY_EMPTY;
    for (unsigned j = i; j < N_NODES; j += stride) g_cnt[j] = 0;
    if (i < D * D) g_W[i] = 0.5f * (W1[i] + W2[i]);
    if (i < D) g_bias[i] = 0.5f * (b1[i] + b2[i]);
}

// ---------------------------------------------------------------------------
// 2. insert edge keys into hash set + symmetrized incidence histogram
// ---------------------------------------------------------------------------
__global__ void k_insert(const int* __restrict__ ei) {
    int e = blockIdx.x * blockDim.x + threadIdx.x;
    if (e >= N_EDGES) return;
    unsigned row = (unsigned)ei[e];
    unsigned col = (unsigned)ei[N_EDGES + e];
    unsigned key = row * (unsigned)N_NODES + col;
    unsigned h = hash_u32(key);
    while (true) {
        unsigned prev = atomicCAS(&g_hash[h], HKEY_EMPTY, key);
        if (prev == HKEY_EMPTY || prev == key) break;
        h = (h + 1u) & HASH_MASK;
    }
    atomicAdd(&g_cnt[row], 1);
    atomicAdd(&g_cnt[col], 1);
}

// ---------------------------------------------------------------------------
// 3. exclusive scan of g_cnt -> g_off / g_next ; dinv folded into pass c
// ---------------------------------------------------------------------------
__global__ void k_scan_a() {
    __shared__ int sh[SCAN_B];
    int i = blockIdx.x * SCAN_B + threadIdx.x;
    sh[threadIdx.x] = (i < N_NODES) ? g_cnt[i] : 0;
    __syncthreads();
    for (int s = SCAN_B / 2; s > 0; s >>= 1) {
        if (threadIdx.x < s) sh[threadIdx.x] += sh[threadIdx.x + s];
        __syncthreads();
    }
    if (threadIdx.x == 0) g_bsum[blockIdx.x] = sh[0];
}
__global__ void k_scan_b() {
    if (threadIdx.x == 0) {
        int acc = 0;
        for (int b = 0; b < NSCAN_BLK; b++) { g_boff[b] = acc; acc += g_bsum[b]; }
    }
}
__global__ void k_scan_c() {
    __shared__ int sh[SCAN_B];
    int i = blockIdx.x * SCAN_B + threadIdx.x;
    int v = (i < N_NODES) ? g_cnt[i] : 0;
    sh[threadIdx.x] = v;
    __syncthreads();
    for (int s = 1; s < SCAN_B; s <<= 1) {
        int t = (threadIdx.x >= s) ? sh[threadIdx.x - s] : 0;
        __syncthreads();
        sh[threadIdx.x] += t;
        __syncthreads();
    }
    int excl = sh[threadIdx.x] - v + g_boff[blockIdx.x];
    if (i < N_NODES) {
        g_off[i] = excl;
        g_next[i] = excl;
        g_dinv[i] = (v > 0) ? rsqrtf(0.5f * (float)v) : 0.f;
    }
    if (i == N_NODES - 1) g_off[N_NODES] = excl + v;
}

// ---------------------------------------------------------------------------
// 4. scatter packed CSR entries (probe hash once per directed edge)
//    2*pi*Q = pi/2  =>  has_rev ? real(+s both dirs) : imag(+s fwd, -s rev)
// ---------------------------------------------------------------------------
__global__ void k_scatter(const int* __restrict__ ei) {
    int e = blockIdx.x * blockDim.x + threadIdx.x;
    if (e >= N_EDGES) return;
    unsigned row = (unsigned)ei[e];
    unsigned col = (unsigned)ei[N_EDGES + e];
    unsigned rkey = col * (unsigned)N_NODES + row;
    unsigned h = hash_u32(rkey);
    unsigned v;
    while ((v = g_hash[h]) != HKEY_EMPTY && v != rkey) h = (h + 1u) & HASH_MASK;
    unsigned hr = (v == rkey) ? 0x10000u : 0u;
    int p1 = atomicAdd(&g_next[row], 1);
    g_ent[p1] = col | hr;                 // forward copy into row's list, sign +
    int p2 = atomicAdd(&g_next[col], 1);
    g_ent[p2] = row | hr | 0x20000u;      // reversed copy into col's list, sign -
}

// ---------------------------------------------------------------------------
// 5. Z = x @ W -> fp16  (40000x128 @ 128x128), 64x128 tile, 256 threads
// ---------------------------------------------------------------------------
__global__ void k_gemm(const float* __restrict__ x) {
    __shared__ float As[64 * 32];
    __shared__ float Bs[32 * 128];

    const int tid = threadIdx.x;
    const int tx = tid & 31;
    const int ty = tid >> 5;
    const int block_row = blockIdx.x * 64;

    float acc[8][4];
#pragma unroll
    for (int i = 0; i < 8; i++)
#pragma unroll
        for (int j = 0; j < 4; j++) acc[i][j] = 0.f;

    const float4* X4 = reinterpret_cast<const float4*>(x);
    const float4* W4 = reinterpret_cast<const float4*>(g_W);
    float4* As4 = reinterpret_cast<float4*>(As);
    float4* Bs4 = reinterpret_cast<float4*>(Bs);

#pragma unroll
    for (int kb = 0; kb < D / 32; kb++) {
#pragma unroll
        for (int q = 0; q < 2; q++) {
            int idx = tid + 256 * q;
            int r = idx >> 3, kp = idx & 7;
            As4[r * 8 + kp] = X4[(size_t)(block_row + r) * (D / 4) + kb * 8 + kp];
        }
#pragma unroll
        for (int q = 0; q < 4; q++) {
            int idx = tid + 256 * q;
            int r = idx >> 5, c4 = idx & 31;
            Bs4[r * 32 + c4] = W4[(size_t)(kb * 32 + r) * (D / 4) + c4];
        }
        __syncthreads();
#pragma unroll
        for (int kk = 0; kk < 32; kk++) {
            float a_[8];
#pragma unroll
            for (int i = 0; i < 8; i++) a_[i] = As[(ty * 8 + i) * 32 + kk];
            float4 b_ = Bs4[kk * 32 + tx];
#pragma unroll
            for (int i = 0; i < 8; i++) {
                acc[i][0] = fmaf(a_[i], b_.x, acc[i][0]);
                acc[i][1] = fmaf(a_[i], b_.y, acc[i][1]);
                acc[i][2] = fmaf(a_[i], b_.z, acc[i][2]);
                acc[i][3] = fmaf(a_[i], b_.w, acc[i][3]);
            }
        }
        __syncthreads();
    }

    // epilogue: convert to fp16, 4 cols per thread -> uint2
    uint2* Z2 = reinterpret_cast<uint2*>(g_Zh);
#pragma unroll
    for (int i = 0; i < 8; i++) {
        int g = block_row + ty * 8 + i;
        __half2 lo = __floats2half2_rn(acc[i][0], acc[i][1]);
        __half2 hi = __floats2half2_rn(acc[i][2], acc[i][3]);
        uint2 packed;
        packed.x = *reinterpret_cast<unsigned*>(&lo);
        packed.y = *reinterpret_cast<unsigned*>(&hi);
        Z2[(size_t)g * 32 + tx] = packed;   // row = 128 half = 32 uint2
    }
}

// ---------------------------------------------------------------------------
// 6. CSR aggregation: one warp per node, fp16 Z gathers in unrolled groups
//    of 4 (MLP>=4), fp32 accumulate, single out-row write (+bias).
// ---------------------------------------------------------------------------
__global__ void k_spmm_csr(float* __restrict__ out) {
    int u = blockIdx.x * (blockDim.x >> 5) + (threadIdx.x >> 5);
    int lane = threadIdx.x & 31;
    if (u >= N_NODES) return;

    int start = g_off[u];
    int end = g_off[u + 1];
    float du = 0.5f * g_dinv[u];

    const uint2* Z2 = reinterpret_cast<const uint2*>(g_Zh);
    float4 are = make_float4(0.f, 0.f, 0.f, 0.f);
    float4 aim = make_float4(0.f, 0.f, 0.f, 0.f);

    for (int base = start; base < end; base += 32) {
        int idx = base + lane;
        bool valid = idx < end;
        unsigned ent = valid ? g_ent[idx] : 0u;
        float w = valid ? du * g_dinv[ent & 0xFFFFu] : 0.f;
        int n = min(32, end - base);
        for (int j0 = 0; j0 < n; j0 += 4) {
            unsigned ee[4];
            float ww[4];
            uint2 zz[4];
#pragma unroll
            for (int t = 0; t < 4; t++) {
                ee[t] = __shfl_sync(0xFFFFFFFFu, ent, j0 + t);
                ww[t] = __shfl_sync(0xFFFFFFFFu, w, j0 + t);
                zz[t] = Z2[(size_t)(ee[t] & 0xFFFFu) * 32 + lane];
            }
#pragma unroll
            for (int t = 0; t < 4; t++) {
                float s = ww[t];
                __half2 h0 = *reinterpret_cast<__half2*>(&zz[t].x);
                __half2 h1 = *reinterpret_cast<__half2*>(&zz[t].y);
                float2 f0 = __half22float2(h0);
                float2 f1 = __half22float2(h1);
                if (ee[t] & 0x10000u) {
                    are.x = fmaf(s, f0.x, are.x); are.y = fmaf(s, f0.y, are.y);
                    are.z = fmaf(s, f1.x, are.z); are.w = fmaf(s, f1.y, are.w);
                } else {
                    if (ee[t] & 0x20000u) s = -s;
                    aim.x = fmaf(s, f0.x, aim.x); aim.y = fmaf(s, f0.y, aim.y);
                    aim.z = fmaf(s, f1.x, aim.z); aim.w = fmaf(s, f1.y, aim.w);
                }
            }
        }
    }

    float4 bias = reinterpret_cast<const float4*>(g_bias)[lane];
    float4* O4 = reinterpret_cast<float4*>(out);
    // out row: [u, 0:128) = re, [u, 128:256) = im ; row = 64 float4
    O4[(size_t)u * 64 + lane] =
        make_float4(are.x + bias.x, are.y + bias.y, are.z + bias.z, are.w + bias.w);
    O4[(size_t)u * 64 + 32 + lane] =
        make_float4(aim.x + bias.x, aim.y + bias.y, aim.z + bias.z, aim.w + bias.w);
}

// ---------------------------------------------------------------------------
extern "C" void kernel_launch(void* const* d_in, const int* in_sizes, int n_in,
                              void* d_out, int out_size) {
    const float* x  = (const float*)d_in[0];
    const int*   ei = (const int*)d_in[1];
    const float* W1 = (const float*)d_in[2];
    const float* b1 = (const float*)d_in[3];
    const float* W2 = (const float*)d_in[4];
    const float* b2 = (const float*)d_in[5];
    float* out = (float*)d_out;

    k_init<<<512, 256>>>(W1, b1, W2, b2);
    k_insert<<<(N_EDGES + 255) / 256, 256>>>(ei);
    k_scan_a<<<NSCAN_BLK, SCAN_B>>>();
    k_scan_b<<<1, 32>>>();
    k_scan_c<<<NSCAN_BLK, SCAN_B>>>();
    k_scatter<<<(N_EDGES + 255) / 256, 256>>>(ei);
    k_gemm<<<N_NODES / 64, 256>>>(x);
    k_spmm_csr<<<(N_NODES + 15) / 16, 512>>>(out);
}

// round 7
// speedup vs baseline: 1.8008x; 1.1094x over previous
#include <cuda_runtime.h>
#include <cuda_fp16.h>
#include <mma.h>

#define N_NODES 40000
#define D 128
#define N_EDGES 640000
#define HASH_BITS 21
#define HASH_SIZE (1u << HASH_BITS)
#define HASH_MASK (HASH_SIZE - 1u)
#define HKEY_EMPTY 0xFFFFFFFFu
#define SCAN_B 256
#define NSCAN_BLK ((N_NODES + SCAN_B - 1) / SCAN_B)   // 157 (<= SCAN_B)

// ---- scratch (~25 MB, no allocations allowed) ----
__device__ unsigned g_hash[HASH_SIZE];
__device__ int g_cnt[N_NODES];           // symmetrized incidence count (deg = 0.5*cnt)
__device__ int g_off[N_NODES + 1];       // CSR offsets
__device__ int g_next[N_NODES];          // scatter cursors
__device__ int g_bsum[NSCAN_BLK];
__device__ unsigned g_ent[2 * N_EDGES];  // packed: src(16) | has_rev(1)<<16 | neg(1)<<17
__device__ float g_dinv[N_NODES];
__device__ __align__(16) __half g_Zh[N_NODES * D];  // Z = x @ W, fp16 (10 MB)
__device__ __align__(16) __half g_Wh[D * D];        // 0.5*(W1+W2) in fp16
__device__ float g_bias[D];                          // 0.5*(b1+b2)

__device__ __forceinline__ unsigned hash_u32(unsigned key) {
    return (key * 2654435761u) >> (32 - HASH_BITS);
}

// ---------------------------------------------------------------------------
// 1. init: hash -> EMPTY, cnt -> 0, fold weights (ALPHA = 0.5) to fp16
// ---------------------------------------------------------------------------
__global__ void k_init(const float* __restrict__ W1, const float* __restrict__ b1,
                       const float* __restrict__ W2, const float* __restrict__ b2) {
    unsigned i = blockIdx.x * blockDim.x + threadIdx.x;
    unsigned stride = gridDim.x * blockDim.x;
    for (unsigned j = i; j < HASH_SIZE; j += stride) g_hash[j] = HKEY_EMPTY;
    for (unsigned j = i; j < N_NODES; j += stride) g_cnt[j] = 0;
    if (i < D * D) g_Wh[i] = __float2half(0.5f * (W1[i] + W2[i]));
    if (i < D) g_bias[i] = 0.5f * (b1[i] + b2[i]);
}

// ---------------------------------------------------------------------------
// 2. insert edge keys into hash set + symmetrized incidence histogram
// ---------------------------------------------------------------------------
__global__ void k_insert(const int* __restrict__ ei) {
    int e = blockIdx.x * blockDim.x + threadIdx.x;
    if (e >= N_EDGES) return;
    unsigned row = (unsigned)ei[e];
    unsigned col = (unsigned)ei[N_EDGES + e];
    unsigned key = row * (unsigned)N_NODES + col;
    unsigned h = hash_u32(key);
    while (true) {
        unsigned prev = atomicCAS(&g_hash[h], HKEY_EMPTY, key);
        if (prev == HKEY_EMPTY || prev == key) break;
        h = (h + 1u) & HASH_MASK;
    }
    atomicAdd(&g_cnt[row], 1);
    atomicAdd(&g_cnt[col], 1);
}

// ---------------------------------------------------------------------------
// 3a. per-block sums of g_cnt
// ---------------------------------------------------------------------------
__global__ void k_scan_a() {
    __shared__ int sh[SCAN_B];
    int i = blockIdx.x * SCAN_B + threadIdx.x;
    sh[threadIdx.x] = (i < N_NODES) ? g_cnt[i] : 0;
    __syncthreads();
    for (int s = SCAN_B / 2; s > 0; s >>= 1) {
        if (threadIdx.x < s) sh[threadIdx.x] += sh[threadIdx.x + s];
        __syncthreads();
    }
    if (threadIdx.x == 0) g_bsum[blockIdx.x] = sh[0];
}

// ---------------------------------------------------------------------------
// 3b. per-block exclusive scan; block offset computed in-block by parallel
//     reduction over g_bsum (157 values, L2-hit) — no serial pass kernel.
//     dinv folded in.
// ---------------------------------------------------------------------------
__global__ void k_scan_c() {
    __shared__ int sh[SCAN_B];
    __shared__ int s_boff;
    // phase 1: boff = sum of g_bsum[0 .. blockIdx.x)
    int p = (threadIdx.x < blockIdx.x) ? g_bsum[threadIdx.x] : 0;
    sh[threadIdx.x] = p;
    __syncthreads();
    for (int s = SCAN_B / 2; s > 0; s >>= 1) {
        if (threadIdx.x < s) sh[threadIdx.x] += sh[threadIdx.x + s];
        __syncthreads();
    }
    if (threadIdx.x == 0) s_boff = sh[0];
    __syncthreads();
    // phase 2: intra-block inclusive scan
    int i = blockIdx.x * SCAN_B + threadIdx.x;
    int v = (i < N_NODES) ? g_cnt[i] : 0;
    sh[threadIdx.x] = v;
    __syncthreads();
    for (int s = 1; s < SCAN_B; s <<= 1) {
        int t = (threadIdx.x >= s) ? sh[threadIdx.x - s] : 0;
        __syncthreads();
        sh[threadIdx.x] += t;
        __syncthreads();
    }
    int excl = sh[threadIdx.x] - v + s_boff;
    if (i < N_NODES) {
        g_off[i] = excl;
        g_next[i] = excl;
        g_dinv[i] = (v > 0) ? rsqrtf(0.5f * (float)v) : 0.f;
    }
    if (i == N_NODES - 1) g_off[N_NODES] = excl + v;
}

// ---------------------------------------------------------------------------
// 4. scatter packed CSR entries (probe hash once per directed edge)
//    2*pi*Q = pi/2  =>  has_rev ? real(+s both dirs) : imag(+s fwd, -s rev)
// ---------------------------------------------------------------------------
__global__ void k_scatter(const int* __restrict__ ei) {
    int e = blockIdx.x * blockDim.x + threadIdx.x;
    if (e >= N_EDGES) return;
    unsigned row = (unsigned)ei[e];
    unsigned col = (unsigned)ei[N_EDGES + e];
    unsigned rkey = col * (unsigned)N_NODES + row;
    unsigned h = hash_u32(rkey);
    unsigned v;
    while ((v = g_hash[h]) != HKEY_EMPTY && v != rkey) h = (h + 1u) & HASH_MASK;
    unsigned hr = (v == rkey) ? 0x10000u : 0u;
    int p1 = atomicAdd(&g_next[row], 1);
    g_ent[p1] = col | hr;                 // forward copy into row's list, sign +
    int p2 = atomicAdd(&g_next[col], 1);
    g_ent[p2] = row | hr | 0x20000u;      // reversed copy into col's list, sign -
}

// ---------------------------------------------------------------------------
// 5. Z = x @ W -> fp16 via tensor cores (wmma 16x16x16, fp16 in / fp32 acc).
//    Block = 64x128 output tile, 8 warps in 2x4, warp tile 32x32 (2x2 frags).
//    W (128x128 fp16 = 32 KB) stays in smem for the whole k loop.
// ---------------------------------------------------------------------------
__global__ void k_gemm_tc(const float* __restrict__ x) {
    __shared__ __align__(16) __half sA[64 * 128];    // 16 KB
    __shared__ __align__(16) __half sB[128 * 128];   // 32 KB
    const int tid = threadIdx.x;
    const int warp = tid >> 5;
    const int block_row = blockIdx.x * 64;

    // W -> smem (2048 uint4, 8 per thread)
    const uint4* Wh4 = reinterpret_cast<const uint4*>(g_Wh);
    uint4* sB4 = reinterpret_cast<uint4*>(sB);
#pragma unroll
    for (int q = 0; q < 8; q++) sB4[tid + 256 * q] = Wh4[tid + 256 * q];

    // x tile -> fp16 smem (64x128: 2048 float4, 8 per thread)
    const float4* X4 = reinterpret_cast<const float4*>(x);
    __half2* sA2 = reinterpret_cast<__half2*>(sA);
#pragma unroll
    for (int q = 0; q < 8; q++) {
        int idx = tid + 256 * q;                       // r*32 + c4
        float4 v = X4[(size_t)block_row * 32 + idx];
        sA2[idx * 2]     = __floats2half2_rn(v.x, v.y);
        sA2[idx * 2 + 1] = __floats2half2_rn(v.z, v.w);
    }
    __syncthreads();

    using namespace nvcuda;
    wmma::fragment<wmma::accumulator, 16, 16, 16, float> c[2][2];
#pragma unroll
    for (int i = 0; i < 2; i++)
#pragma unroll
        for (int j = 0; j < 2; j++) wmma::fill_fragment(c[i][j], 0.f);

    const int wm = (warp >> 2) * 32;   // 0 or 32
    const int wn = (warp & 3) * 32;    // 0,32,64,96

#pragma unroll
    for (int k = 0; k < D; k += 16) {
        wmma::fragment<wmma::matrix_a, 16, 16, 16, __half, wmma::row_major> a[2];
        wmma::fragment<wmma::matrix_b, 16, 16, 16, __half, wmma::row_major> b[2];
        wmma::load_matrix_sync(a[0], sA + (wm) * D + k, D);
        wmma::load_matrix_sync(a[1], sA + (wm + 16) * D + k, D);
        wmma::load_matrix_sync(b[0], sB + k * D + wn, D);
        wmma::load_matrix_sync(b[1], sB + k * D + wn + 16, D);
#pragma unroll
        for (int i = 0; i < 2; i++)
#pragma unroll
            for (int j = 0; j < 2; j++)
                wmma::mma_sync(c[i][j], a[i], b[j], c[i][j]);
    }
    __syncthreads();   // done reading sB; reuse as fp32 scratch (64x128 f32 = 32 KB)

    float* scratch = reinterpret_cast<float*>(sB);
#pragma unroll
    for (int i = 0; i < 2; i++)
#pragma unroll
        for (int j = 0; j < 2; j++)
            wmma::store_matrix_sync(scratch + (wm + 16 * i) * D + wn + 16 * j,
                                    c[i][j], D, wmma::mem_row_major);
    __syncthreads();

    // scratch fp32 -> g_Zh fp16 (2048 float4, 8 per thread)
    uint2* Z2 = reinterpret_cast<uint2*>(g_Zh);
    const float4* sc4 = reinterpret_cast<const float4*>(scratch);
#pragma unroll
    for (int q = 0; q < 8; q++) {
        int idx = tid + 256 * q;                       // r*32 + c4
        float4 v = sc4[idx];
        __half2 lo = __floats2half2_rn(v.x, v.y);
        __half2 hi = __floats2half2_rn(v.z, v.w);
        uint2 packed;
        packed.x = *reinterpret_cast<unsigned*>(&lo);
        packed.y = *reinterpret_cast<unsigned*>(&hi);
        Z2[(size_t)block_row * 32 + idx] = packed;
    }
}

// ---------------------------------------------------------------------------
// 6. CSR aggregation: one warp per node, fp16 Z gathers in unrolled groups
//    of 4 (MLP>=4), fp32 accumulate, single out-row write (+bias).
// ---------------------------------------------------------------------------
__global__ void k_spmm_csr(float* __restrict__ out) {
    int u = blockIdx.x * (blockDim.x >> 5) + (threadIdx.x >> 5);
    int lane = threadIdx.x & 31;
    if (u >= N_NODES) return;

    int start = g_off[u];
    int end = g_off[u + 1];
    float du = 0.5f * g_dinv[u];

    const uint2* Z2 = reinterpret_cast<const uint2*>(g_Zh);
    float4 are = make_float4(0.f, 0.f, 0.f, 0.f);
    float4 aim = make_float4(0.f, 0.f, 0.f, 0.f);

    for (int base = start; base < end; base += 32) {
        int idx = base + lane;
        bool valid = idx < end;
        unsigned ent = valid ? g_ent[idx] : 0u;
        float w = valid ? du * g_dinv[ent & 0xFFFFu] : 0.f;
        int n = min(32, end - base);
        for (int j0 = 0; j0 < n; j0 += 4) {
            unsigned ee[4];
            float ww[4];
            uint2 zz[4];
#pragma unroll
            for (int t = 0; t < 4; t++) {
                ee[t] = __shfl_sync(0xFFFFFFFFu, ent, j0 + t);
                ww[t] = __shfl_sync(0xFFFFFFFFu, w, j0 + t);
                zz[t] = Z2[(size_t)(ee[t] & 0xFFFFu) * 32 + lane];
            }
#pragma unroll
            for (int t = 0; t < 4; t++) {
                float s = ww[t];
                __half2 h0 = *reinterpret_cast<__half2*>(&zz[t].x);
                __half2 h1 = *reinterpret_cast<__half2*>(&zz[t].y);
                float2 f0 = __half22float2(h0);
                float2 f1 = __half22float2(h1);
                if (ee[t] & 0x10000u) {
                    are.x = fmaf(s, f0.x, are.x); are.y = fmaf(s, f0.y, are.y);
                    are.z = fmaf(s, f1.x, are.z); are.w = fmaf(s, f1.y, are.w);
                } else {
                    if (ee[t] & 0x20000u) s = -s;
                    aim.x = fmaf(s, f0.x, aim.x); aim.y = fmaf(s, f0.y, aim.y);
                    aim.z = fmaf(s, f1.x, aim.z); aim.w = fmaf(s, f1.y, aim.w);
                }
            }
        }
    }

    float4 bias = reinterpret_cast<const float4*>(g_bias)[lane];
    float4* O4 = reinterpret_cast<float4*>(out);
    // out row: [u, 0:128) = re, [u, 128:256) = im ; row = 64 float4
    O4[(size_t)u * 64 + lane] =
        make_float4(are.x + bias.x, are.y + bias.y, are.z + bias.z, are.w + bias.w);
    O4[(size_t)u * 64 + 32 + lane] =
        make_float4(aim.x + bias.x, aim.y + bias.y, aim.z + bias.z, aim.w + bias.w);
}

// ---------------------------------------------------------------------------
extern "C" void kernel_launch(void* const* d_in, const int* in_sizes, int n_in,
                              void* d_out, int out_size) {
    const float* x  = (const float*)d_in[0];
    const int*   ei = (const int*)d_in[1];
    const float* W1 = (const float*)d_in[2];
    const float* b1 = (const float*)d_in[3];
    const float* W2 = (const float*)d_in[4];
    const float* b2 = (const float*)d_in[5];
    float* out = (float*)d_out;

    k_init<<<512, 256>>>(W1, b1, W2, b2);
    k_insert<<<(N_EDGES + 255) / 256, 256>>>(ei);
    k_scan_a<<<NSCAN_BLK, SCAN_B>>>();
    k_scan_c<<<NSCAN_BLK, SCAN_B>>>();
    k_scatter<<<(N_EDGES + 255) / 256, 256>>>(ei);
    k_gemm_tc<<<N_NODES / 64, 256>>>(x);
    k_spmm_csr<<<(N_NODES + 15) / 16, 512>>>(out);
}